// round 2
// baseline (speedup 1.0000x reference)
#include <cuda_runtime.h>
#include <cuda_bf16.h>

#define NTHREADS 256
#define NBLOCKS  1184
#define LVL      64

// Quantize/dequantize (AdaptedEntropyModel):
//   r = x - means
//   pos = clip(searchsorted(cb, r, side='left'), 1, 63)
//   sym = (r - cb[pos-1] <= cb[pos] - r) ? pos-1 : pos
//   y_hat = cb[sym] + means
// Output buffer (out_size == 2N floats): [0..N) = float(sym), [N..2N) = y_hat.
__global__ void __launch_bounds__(NTHREADS)
quant_dequant_kernel(const float4* __restrict__ x4,
                     const float4* __restrict__ m4,
                     const float*  __restrict__ cb,
                     float* __restrict__ out_sym,
                     float* __restrict__ out_y,
                     int n4, int n)
{
    // Lane-private codebook replicas: entry i for lane l lives at s_cb[i*32 + l].
    // Every access in the data-dependent binary search then hits bank==lane:
    // conflict-free (degree 1) regardless of divergence in the search path.
    __shared__ float s_cb[LVL * 32];
    for (int i = threadIdx.x; i < LVL * 32; i += NTHREADS)
        s_cb[i] = cb[i >> 5];
    __syncthreads();

    const int    lane = threadIdx.x & 31;
    const float* mycb = s_cb + lane;           // mycb[idx*32] == cb[idx]

    const int stride = gridDim.x * NTHREADS;

    for (int i = blockIdx.x * NTHREADS + threadIdx.x; i < n4; i += stride) {
        float4 xv = x4[i];
        float4 mv = m4[i];

        float r[4]  = { xv.x - mv.x, xv.y - mv.y, xv.z - mv.z, xv.w - mv.w };
        float mn[4] = { mv.x, mv.y, mv.z, mv.w };
        float sy[4], yy[4];

        #pragma unroll
        for (int j = 0; j < 4; ++j) {
            float rv = r[j];
            // Branchless lower_bound over 64 sorted entries (6 steps).
            // pos = count of cb[k] < rv, structurally capped at 63 by the
            // search (max pos after 6 steps with cand-1 <= 62 checks is 63
            // only via the last step); clip below to 1.
            int pos = 0;
            #pragma unroll
            for (int step = 32; step > 0; step >>= 1) {
                int cand = pos + step;
                if (mycb[(cand - 1) << 5] < rv) pos = cand;
            }
            pos = min(max(pos, 1), LVL - 1);   // clip to [1, 63] like reference
            float left  = mycb[(pos - 1) << 5];
            float right = mycb[pos << 5];
            // Exact tie rule from the reference, same fp32 ops.
            bool take_left = (rv - left) <= (right - rv);
            int   symb = take_left ? (pos - 1) : pos;
            float lvl  = take_left ? left : right;
            sy[j] = (float)symb;
            yy[j] = lvl + mn[j];
        }

        ((float4*)out_sym)[i] = make_float4(sy[0], sy[1], sy[2], sy[3]);
        ((float4*)out_y)[i]   = make_float4(yy[0], yy[1], yy[2], yy[3]);
    }

    // Scalar tail (n not divisible by 4 — not expected here, but safe).
    int tail_start = n4 * 4;
    for (int i = tail_start + blockIdx.x * NTHREADS + threadIdx.x; i < n; i += stride) {
        const float* xs = (const float*)x4;
        const float* ms = (const float*)m4;
        float mvs = ms[i];
        float rv  = xs[i] - mvs;
        int pos = 0;
        #pragma unroll
        for (int step = 32; step > 0; step >>= 1) {
            int cand = pos + step;
            if (mycb[(cand - 1) << 5] < rv) pos = cand;
        }
        pos = min(max(pos, 1), LVL - 1);
        float left  = mycb[(pos - 1) << 5];
        float right = mycb[pos << 5];
        bool take_left = (rv - left) <= (right - rv);
        int   symb = take_left ? (pos - 1) : pos;
        float lvl  = take_left ? left : right;
        out_sym[i] = (float)symb;
        out_y[i]   = lvl + mvs;
    }
}

extern "C" void kernel_launch(void* const* d_in, const int* in_sizes, int n_in,
                              void* d_out, int out_size)
{
    const float* x     = (const float*)d_in[0];   // [B,C,H,W] f32
    const float* means = (const float*)d_in[1];   // [B,C,H,W] f32
    const float* cb    = (const float*)d_in[2];   // [64] f32 sorted

    int n  = in_sizes[0];
    int n4 = n >> 2;

    float* out_sym = (float*)d_out;       // first N floats: symbols (exact in f32)
    float* out_y   = out_sym + n;         // next  N floats: y_hat

    quant_dequant_kernel<<<NBLOCKS, NTHREADS>>>(
        (const float4*)x, (const float4*)means, cb, out_sym, out_y, n4, n);
}